// round 15
// baseline (speedup 1.0000x reference)
#include <cuda_runtime.h>
#include <cuda_fp16.h>
#include <math.h>
#include <stdint.h>

#define B_   4
#define S_   1024
#define D_   1024
#define H_   16
#define HD_  64
#define MTOT (B_*S_)

// ---- scratch (no cudaMalloc allowed) ----
__device__ __align__(16) __half g_Xh[3][MTOT*D_];   // q,k,v inputs in half
__device__ __align__(16) __half g_Wh[4][D_*D_];     // W in half, [k][n]
__device__ __align__(16) __half g_Qh[MTOT*D_];      // [B,H,S,HD]
__device__ __align__(16) __half g_Kh[MTOT*D_];
__device__ __align__(16) __half g_Vh[MTOT*D_];
__device__ __align__(16) __half g_attn_h[MTOT*D_];  // [B,S,D] half
__device__ __align__(16) float  g_proj[MTOT*D_];

__device__ __forceinline__ void mma_f16(float c[4], const uint32_t a[4],
                                        const uint32_t b[2]) {
    asm volatile(
        "mma.sync.aligned.m16n8k16.row.col.f32.f16.f16.f32 "
        "{%0,%1,%2,%3}, {%4,%5,%6,%7}, {%8,%9}, {%0,%1,%2,%3};"
        : "+f"(c[0]), "+f"(c[1]), "+f"(c[2]), "+f"(c[3])
        : "r"(a[0]), "r"(a[1]), "r"(a[2]), "r"(a[3]), "r"(b[0]), "r"(b[1]));
}

__device__ __forceinline__ void ldsm4(uint32_t r[4], const void* p) {
    uint32_t a = (uint32_t)__cvta_generic_to_shared(p);
    asm volatile("ldmatrix.sync.aligned.m8n8.x4.shared.b16 {%0,%1,%2,%3}, [%4];"
                 : "=r"(r[0]), "=r"(r[1]), "=r"(r[2]), "=r"(r[3]) : "r"(a));
}
__device__ __forceinline__ void ldsm4t(uint32_t r[4], const void* p) {
    uint32_t a = (uint32_t)__cvta_generic_to_shared(p);
    asm volatile("ldmatrix.sync.aligned.m8n8.x4.trans.shared.b16 {%0,%1,%2,%3}, [%4];"
                 : "=r"(r[0]), "=r"(r[1]), "=r"(r[2]), "=r"(r[3]) : "r"(a));
}
__device__ __forceinline__ uint32_t packh2(float x, float y) {
    __half2 h = __floats2half2_rn(x, y);
    return *(uint32_t*)&h;
}
__device__ __forceinline__ uint32_t hex2(uint32_t x) {
    uint32_t d;
    asm("ex2.approx.f16x2 %0, %1;" : "=r"(d) : "r"(x));
    return d;
}
__device__ __forceinline__ float fex2(float x) {
    float d;
    asm("ex2.approx.f32 %0, %1;" : "=f"(d) : "f"(x));
    return d;
}
__device__ __forceinline__ void cp16(void* smem, const void* gmem) {
    uint32_t s = (uint32_t)__cvta_generic_to_shared(smem);
    asm volatile("cp.async.cg.shared.global [%0], [%1], 16;\n" :: "r"(s), "l"(gmem));
}
__device__ __forceinline__ void cp_commit() {
    asm volatile("cp.async.commit_group;\n");
}
__device__ __forceinline__ void cp_wait1() {
    asm volatile("cp.async.wait_group 1;\n");
}
__device__ __forceinline__ void cp_wait2() {
    asm volatile("cp.async.wait_group 2;\n");
}

// ============================================================
// fused converters (both branches pure streaming converts)
// ============================================================
#define CONV_IN_BLKS (3 * (MTOT * D_ / 1024))
#define CONV_W_BLKS  (4 * (D_ * D_ / 1024))

__global__ __launch_bounds__(256) void conv_kernel(
    const float* __restrict__ q, const float* __restrict__ k,
    const float* __restrict__ v,
    const float* __restrict__ Wq, const float* __restrict__ Wk,
    const float* __restrict__ Wv, const float* __restrict__ Wo)
{
    const int blk = blockIdx.x;
    const float* src;
    __half* dst;
    int i;
    if (blk < CONV_IN_BLKS) {
        const int z  = blk / (MTOT * D_ / 1024);
        const int bx = blk % (MTOT * D_ / 1024);
        src = (z == 0) ? q : (z == 1) ? k : v;
        dst = g_Xh[z];
        i = (bx * 256 + threadIdx.x) * 4;
    } else {
        const int r  = blk - CONV_IN_BLKS;
        const int z  = r >> 10;
        const int bx = r & 1023;
        src = (z == 0) ? Wq : (z == 1) ? Wk : (z == 2) ? Wv : Wo;
        dst = g_Wh[z];
        i = (bx * 256 + threadIdx.x) * 4;
    }
    float4 f = *(const float4*)(src + i);
    *(__half2*)(dst + i)     = __floats2half2_rn(f.x, f.y);
    *(__half2*)(dst + i + 2) = __floats2half2_rn(f.z, f.w);
}

// ============================================================
// fp16 tensor-core GEMM: out = X[M,1024] @ W[1024,1024] + bias
// W stored [k][n]; B fragments via ldmatrix.trans.
// BK=32, 3-stage cp.async pipeline with wait_group 2 (2-deep),
// refill post-compute. 4 warps, warp tile 64x64. Dynamic smem.
// ============================================================
#define GA_PITCH 40
#define GB_PITCH 136
#define GA_STAGE (128 * GA_PITCH)     // halfs
#define GB_STAGE (32 * GB_PITCH)      // halfs
#define GEMM_SMEM ((3 * GA_STAGE + 3 * GB_STAGE) * 2)   // 56832 bytes

template <int MODE>
__device__ __forceinline__ void gemm_f16_body(
    const __half* __restrict__ X, const __half* __restrict__ Wn,
    const float* __restrict__ bias, void* outp)
{
    extern __shared__ __align__(16) __half gsm[];
    __half* As = gsm;                      // [3][128][40]
    __half* Bs = gsm + 3 * GA_STAGE;       // [3][32][136]

    const int tid    = threadIdx.x;      // 0..127
    const int wid    = tid >> 5;         // 0..3
    const int lane   = tid & 31;
    const int warp_m = wid & 1;
    const int warp_n = wid >> 1;
    const int g      = lane >> 2;
    const int tg     = lane & 3;

    const int row0 = blockIdx.y * 128;
    const int col0 = blockIdx.x * 128;

    const int lrow = tid >> 1;           // 0..63
    const int loff = (tid & 1) * 16;

    const __half* Abase = X + (size_t)(row0 + lrow) * D_ + loff;

    auto load_stage = [&](int s, int k0) {
        __half* Ad = As + s * GA_STAGE;
        __half* Bd = Bs + s * GB_STAGE;
        #pragma unroll
        for (int p = 0; p < 2; p++) {
            const int r = p * 64;
            cp16(Ad + (lrow + r) * GA_PITCH + loff,     Abase + (size_t)r * D_ + k0);
            cp16(Ad + (lrow + r) * GA_PITCH + loff + 8, Abase + (size_t)r * D_ + k0 + 8);
        }
        #pragma unroll
        for (int qch = 0; qch < 4; qch++) {
            const int c  = qch * 128 + tid;
            const int br = c >> 4;            // 0..31 (k)
            const int bc = (c & 15) * 8;      // 0..120 (n)
            cp16(Bd + br * GB_PITCH + bc, Wn + (size_t)(k0 + br) * D_ + col0 + bc);
        }
        cp_commit();
    };

    load_stage(0, 0);
    load_stage(1, 32);
    load_stage(2, 64);

    float acc[4][8][4];
    #pragma unroll
    for (int mt = 0; mt < 4; mt++)
        #pragma unroll
        for (int nt = 0; nt < 8; nt++)
            #pragma unroll
            for (int i = 0; i < 4; i++) acc[mt][nt][i] = 0.f;

    const int a_r = lane & 15;
    const int a_c = ((lane >> 4) & 1) * 8;
    const int t_r = ((lane >> 3) & 1) * 8 + (lane & 7);   // trans row (k)
    const int t_c = ((lane >> 4) & 1) * 8;                // trans col (n)

    const int NIT = D_ / 32;   // 32
    for (int it = 0; it < NIT; it++) {
        cp_wait2();            // stage it landed (<=2 groups pending)
        __syncthreads();
        const int s = it % 3;
        const __half* Ab = As + s * GA_STAGE;
        const __half* Bb = Bs + s * GB_STAGE;

        #pragma unroll
        for (int ks = 0; ks < 2; ks++) {
            const int kb = ks * 16;
            uint32_t af[4][4];
            #pragma unroll
            for (int mt = 0; mt < 4; mt++)
                ldsm4(af[mt], Ab + (warp_m*64 + mt*16 + a_r) * GA_PITCH + kb + a_c);
            uint32_t bf[8][2];
            #pragma unroll
            for (int ntp = 0; ntp < 4; ntp++) {
                uint32_t t[4];
                ldsm4t(t, Bb + (kb + t_r) * GB_PITCH + warp_n*64 + ntp*16 + t_c);
                bf[2*ntp][0]   = t[0]; bf[2*ntp][1]   = t[1];
                bf[2*ntp+1][0] = t[2]; bf[2*ntp+1][1] = t[3];
            }
            #pragma unroll
            for (int mt = 0; mt < 4; mt++)
                #pragma unroll
                for (int nt = 0; nt < 8; nt++)
                    mma_f16(acc[mt][nt], af[mt], bf[nt]);
        }
        __syncthreads();       // all warps done with stage it before refill
        const int knext = (it + 3 < NIT) ? (it + 3) * 32 : 0;
        load_stage(s, knext);
    }

    #pragma unroll
    for (int nt = 0; nt < 8; nt++) {
        const int c  = col0 + warp_n * 64 + nt * 8 + tg * 2;
        const float bx = bias[c];
        const float by = bias[c + 1];
        #pragma unroll
        for (int mt = 0; mt < 4; mt++) {
            const int r = row0 + warp_m * 64 + mt * 16 + g;
            if (MODE == 0) {
                __half* oh = (__half*)outp;
                __half2 v0 = __floats2half2_rn(acc[mt][nt][0] + bx, acc[mt][nt][1] + by);
                __half2 v1 = __floats2half2_rn(acc[mt][nt][2] + bx, acc[mt][nt][3] + by);
                const int h = c >> 6, d = c & 63;
                const int b0 = r >> 10,       s0 = r & (S_ - 1);
                const int b1 = (r + 8) >> 10, s1 = (r + 8) & (S_ - 1);
                *(__half2*)(&oh[(((size_t)(b0 * H_ + h)) * S_ + s0) * HD_ + d]) = v0;
                *(__half2*)(&oh[(((size_t)(b1 * H_ + h)) * S_ + s1) * HD_ + d]) = v1;
            } else {
                float* of = (float*)outp;
                float2 v0 = make_float2(acc[mt][nt][0] + bx, acc[mt][nt][1] + by);
                float2 v1 = make_float2(acc[mt][nt][2] + bx, acc[mt][nt][3] + by);
                *(float2*)(&of[(size_t)r * D_ + c])       = v0;
                *(float2*)(&of[(size_t)(r + 8) * D_ + c]) = v1;
            }
        }
    }
}

__global__ __launch_bounds__(128, 2) void qkv_proj_kernel(
    const float* __restrict__ bq, const float* __restrict__ bk,
    const float* __restrict__ bv)
{
    const int z = blockIdx.z;
    const float* bias = (z == 0) ? bq : (z == 1) ? bk : bv;
    __half* outp = (z == 0) ? g_Qh : (z == 1) ? g_Kh : g_Vh;
    gemm_f16_body<0>(g_Xh[z], g_Wh[z], bias, outp);
}

__global__ __launch_bounds__(128, 2) void out_proj_kernel(const float* __restrict__ bo)
{
    gemm_f16_body<1>(g_attn_h, g_Wh[3], bo, g_proj);
}

// ============================================================
// Flash attention (causal), fp16 TC, log2-domain softmax.
// Paired q-tiles (p, 7-p): every CTA = 18 KV-tile iterations,
// grid 4x64 = 256 CTAs = one balanced wave at 2 CTAs/SM.
// ============================================================
#define C_LOG2E 0.18033688011112042f   // 0.125 * log2(e)

__global__ __launch_bounds__(256, 2) void attn_kernel(const int* __restrict__ mask)
{
    __shared__ __align__(16) __half Ks[2][64][72];
    __shared__ __align__(16) __half Vs[2][64][72];
    __shared__ __align__(16) int    Msk[2][64];

    const int pr = blockIdx.x;        // 0..3
    const int bh = blockIdx.y;
    const int b  = bh >> 4;
    const int h  = bh & 15;

    const int tid  = threadIdx.x;
    const int wid  = tid >> 5;
    const int lane = tid & 31;
    const int g    = lane >> 2;
    const int tg   = lane & 3;
    const int m0   = wid * 16;

    const __half* __restrict__ Qg = g_Qh + (size_t)bh * S_ * HD_;
    const __half* __restrict__ Kg = g_Kh + (size_t)bh * S_ * HD_;
    const __half* __restrict__ Vg = g_Vh + (size_t)bh * S_ * HD_;
    const int* __restrict__ mrow  = mask + b * S_;

    const int fr = tid >> 2;
    const int fc = (tid & 3) * 16;

    auto load_kv = [&](int j, int buf) {
        const __half* Krow = Kg + (size_t)(j*64 + fr) * HD_ + fc;
        const __half* Vrow = Vg + (size_t)(j*64 + fr) * HD_ + fc;
        cp16(&Ks[buf][fr][fc],     Krow);
        cp16(&Ks[buf][fr][fc + 8], Krow + 8);
        cp16(&Vs[buf][fr][fc],     Vrow);
        cp16(&Vs[buf][fr][fc + 8], Vrow + 8);
        if (tid < 16)
            cp16(&Msk[buf][tid * 4], mrow + j*64 + tid*4);
        cp_commit();
    };

    const int b_r = ((lane >> 4) & 1) * 8 + (lane & 7);
    const int b_c = ((lane >> 3) & 1) * 8;
    const int vrow_off = ((lane >> 3) & 1) * 8 + (lane & 7);
    const int vcol_off = ((lane >> 4) & 1) * 8;
    const uint32_t ONES_B[2] = {0x3C003C00u, 0x3C003C00u};

    #pragma unroll 1
    for (int half = 0; half < 2; half++) {
        const int qt   = (half == 0) ? (7 - pr) : pr;   // heavy first
        const int jmax = 2*qt + 1;

        load_kv(0, 0);
        load_kv(1, 1);

        const int qr0 = qt*128 + m0 + g;
        uint32_t qf[4][4];
        {
            const __half* q0 = Qg + (size_t)qr0 * HD_ + 2*tg;
            const __half* q1 = Qg + (size_t)(qr0 + 8) * HD_ + 2*tg;
            #pragma unroll
            for (int ks = 0; ks < 4; ks++) {
                qf[ks][0] = *(const uint32_t*)(q0 + ks*16);
                qf[ks][1] = *(const uint32_t*)(q1 + ks*16);
                qf[ks][2] = *(const uint32_t*)(q0 + ks*16 + 8);
                qf[ks][3] = *(const uint32_t*)(q1 + ks*16 + 8);
            }
        }

        float m_i[2] = {-1e30f, -1e30f};
        float lacc[4] = {0.f, 0.f, 0.f, 0.f};
        float o[8][4];
        #pragma unroll
        for (int dt = 0; dt < 8; dt++)
            #pragma unroll
            for (int i = 0; i < 4; i++) o[dt][i] = 0.f;

        for (int j = 0; j <= jmax; j++) {
            const int buf = j & 1;
            cp_wait1();
            __syncthreads();

            // ---- S = Q K^T (16x64 per warp)
            float s[8][4];
            #pragma unroll
            for (int nt = 0; nt < 8; nt++)
                #pragma unroll
                for (int i = 0; i < 4; i++) s[nt][i] = 0.f;

            #pragma unroll
            for (int ks = 0; ks < 4; ks++) {
                const int kb = ks * 16;
                #pragma unroll
                for (int ntp = 0; ntp < 4; ntp++) {
                    uint32_t t[4];
                    ldsm4(t, &Ks[buf][ntp*16 + b_r][kb + b_c]);
                    uint32_t bfa[2] = {t[0], t[1]};
                    uint32_t bfb[2] = {t[2], t[3]};
                    mma_f16(s[2*ntp],     qf[ks], bfa);
                    mma_f16(s[2*ntp + 1], qf[ks], bfb);
                }
            }

            // ---- scale (log2 domain) + mask
            const bool diag = (j*64 + 63) > (qt*128 + m0);
            #pragma unroll
            for (int nt = 0; nt < 8; nt++) {
                const int c0 = nt*8 + 2*tg;
                const float ma = (Msk[buf][c0]     == 0) ? -1e9f : 0.f;
                const float mb = (Msk[buf][c0 + 1] == 0) ? -1e9f : 0.f;
                s[nt][0] = s[nt][0] * C_LOG2E + ma;
                s[nt][1] = s[nt][1] * C_LOG2E + mb;
                s[nt][2] = s[nt][2] * C_LOG2E + ma;
                s[nt][3] = s[nt][3] * C_LOG2E + mb;
                if (diag) {
                    const int gc0 = j*64 + c0;
                    if (gc0 > qr0)         s[nt][0] = -1e9f;
                    if (gc0 + 1 > qr0)     s[nt][1] = -1e9f;
                    if (gc0 > qr0 + 8)     s[nt][2] = -1e9f;
                    if (gc0 + 1 > qr0 + 8) s[nt][3] = -1e9f;
                }
            }

            // ---- online max (rows g, g+8)
            float rm0 = -1e30f, rm1 = -1e30f;
            #pragma unroll
            for (int nt = 0; nt < 8; nt++) {
                rm0 = fmaxf(rm0, fmaxf(s[nt][0], s[nt][1]));
                rm1 = fmaxf(rm1, fmaxf(s[nt][2], s[nt][3]));
            }
            rm0 = fmaxf(rm0, __shfl_xor_sync(0xffffffffu, rm0, 1));
            rm0 = fmaxf(rm0, __shfl_xor_sync(0xffffffffu, rm0, 2));
            rm1 = fmaxf(rm1, __shfl_xor_sync(0xffffffffu, rm1, 1));
            rm1 = fmaxf(rm1, __shfl_xor_sync(0xffffffffu, rm1, 2));

            const float mn0 = fmaxf(m_i[0], rm0);
            const float mn1 = fmaxf(m_i[1], rm1);
            const float corr0 = fex2(m_i[0] - mn0);
            const float corr1 = fex2(m_i[1] - mn1);
            m_i[0] = mn0; m_i[1] = mn1;

            // ---- P fragments via ex2.f16x2
            uint32_t af[4][4];
            #pragma unroll
            for (int ks = 0; ks < 4; ks++) {
                af[ks][0] = hex2(packh2(s[2*ks][0]     - mn0, s[2*ks][1]     - mn0));
                af[ks][1] = hex2(packh2(s[2*ks][2]     - mn1, s[2*ks][3]     - mn1));
                af[ks][2] = hex2(packh2(s[2*ks + 1][0] - mn0, s[2*ks + 1][1] - mn0));
                af[ks][3] = hex2(packh2(s[2*ks + 1][2] - mn1, s[2*ks + 1][3] - mn1));
            }

            // ---- rescale O and l by corr
            #pragma unroll
            for (int dt = 0; dt < 8; dt++) {
                o[dt][0] *= corr0; o[dt][1] *= corr0;
                o[dt][2] *= corr1; o[dt][3] *= corr1;
            }
            lacc[0] *= corr0; lacc[1] *= corr0;
            lacc[2] *= corr1; lacc[3] *= corr1;

            // ---- O += P @ V ; l += P @ ones
            #pragma unroll
            for (int ks = 0; ks < 4; ks++) {
                mma_f16(lacc, af[ks], ONES_B);
                #pragma unroll
                for (int dt2 = 0; dt2 < 4; dt2++) {
                    uint32_t t[4];
                    ldsm4t(t, &Vs[buf][ks*16 + vrow_off][dt2*16 + vcol_off]);
                    uint32_t bfa[2] = {t[0], t[1]};
                    uint32_t bfb[2] = {t[2], t[3]};
                    mma_f16(o[dt2*2],     af[ks], bfa);
                    mma_f16(o[dt2*2 + 1], af[ks], bfb);
                }
            }

            __syncthreads();
            const int jn = (j + 2 <= jmax) ? j + 2 : 0;
            load_kv(jn, buf);
        }

        const float inv0 = 1.f / lacc[0];
        const float inv1 = 1.f / lacc[2];
        #pragma unroll
        for (int dt = 0; dt < 8; dt++) {
            const int c = h*64 + dt*8 + 2*tg;
            *(__half2*)(&g_attn_h[((size_t)(b*S_ + qr0))*D_ + c]) =
                __floats2half2_rn(o[dt][0] * inv0, o[dt][1] * inv0);
            *(__half2*)(&g_attn_h[((size_t)(b*S_ + qr0 + 8))*D_ + c]) =
                __floats2half2_rn(o[dt][2] * inv1, o[dt][3] * inv1);
        }
    }
}

// ============================================================
// Residual add + LayerNorm, float4-vectorized, row in registers.
// ============================================================
__global__ __launch_bounds__(256) void ln_kernel(
    const float* __restrict__ query,
    const float* __restrict__ lw, const float* __restrict__ lb,
    float* __restrict__ out)
{
    __shared__ float red[8];
    const int r   = blockIdx.x;
    const int tid = threadIdx.x;
    const size_t base = (size_t)r * D_;

    float4 a = *(const float4*)(g_proj + base + tid * 4);
    float4 qv = *(const float4*)(query + base + tid * 4);
    float4 x;
    x.x = a.x + qv.x; x.y = a.y + qv.y;
    x.z = a.z + qv.z; x.w = a.w + qv.w;

    float s = x.x + x.y + x.z + x.w;
    #pragma unroll
    for (int off = 16; off >= 1; off >>= 1) s += __shfl_xor_sync(~0u, s, off);
    if ((tid & 31) == 0) red[tid >> 5] = s;
    __syncthreads();
    if (tid < 32) {
        float t = (tid < 8) ? red[tid] : 0.f;
        #pragma unroll
        for (int off = 4; off >= 1; off >>= 1) t += __shfl_xor_sync(~0u, t, off);
        if (tid == 0) red[0] = t;
    }
    __syncthreads();
    const float mean = red[0] * (1.f / (float)D_);
    __syncthreads();

    float4 d;
    d.x = x.x - mean; d.y = x.y - mean;
    d.z = x.z - mean; d.w = x.w - mean;
    float sv = d.x*d.x + d.y*d.y + d.z*d.z + d.w*d.w;
    #pragma unroll
    for (int off = 16; off >= 1; off >>= 1) sv += __shfl_xor_sync(~0u, sv, off);
    if ((tid & 31) == 0) red[tid >> 5] = sv;
    __syncthreads();
    if (tid < 32) {
        float t = (tid < 8) ? red[tid] : 0.f;
        #pragma unroll
        for (int off = 4; off >= 1; off >>= 1) t += __shfl_xor_sync(~0u, t, off);
        if (tid == 0) red[0] = t;
    }
    __syncthreads();
    const float var = red[0] * (1.f / (float)(D_ - 1));
    const float inv = 1.f / (sqrtf(var) + 1e-6f);

    float4 w = *(const float4*)(lw + tid * 4);
    float4 bb = *(const float4*)(lb + tid * 4);
    float4 o;
    o.x = w.x * d.x * inv + bb.x;
    o.y = w.y * d.y * inv + bb.y;
    o.z = w.z * d.z * inv + bb.z;
    o.w = w.w * d.w * inv + bb.w;
    *(float4*)(out + base + tid * 4) = o;
}

// ============================================================
extern "C" void kernel_launch(void* const* d_in, const int* in_sizes, int n_in,
                              void* d_out, int out_size)
{
    const float* query = (const float*)d_in[0];
    const float* key   = (const float*)d_in[1];
    const float* value = (const float*)d_in[2];
    const int*   mask  = (const int*)  d_in[3];
    const float* Wq    = (const float*)d_in[4];
    const float* bq    = (const float*)d_in[5];
    const float* Wk    = (const float*)d_in[6];
    const float* bk    = (const float*)d_in[7];
    const float* Wv    = (const float*)d_in[8];
    const float* bv    = (const float*)d_in[9];
    const float* Wo    = (const float*)d_in[10];
    const float* bo    = (const float*)d_in[11];
    const float* ln_w  = (const float*)d_in[12];
    const float* ln_b  = (const float*)d_in[13];
    float* out = (float*)d_out;

    cudaFuncSetAttribute(qkv_proj_kernel,
                         cudaFuncAttributeMaxDynamicSharedMemorySize, GEMM_SMEM);
    cudaFuncSetAttribute(out_proj_kernel,
                         cudaFuncAttributeMaxDynamicSharedMemorySize, GEMM_SMEM);

    conv_kernel<<<CONV_IN_BLKS + CONV_W_BLKS, 256>>>(query, key, value,
                                                     Wq, Wk, Wv, Wo);
    qkv_proj_kernel<<<dim3(8, 32, 3), 128, GEMM_SMEM>>>(bq, bk, bv);
    attn_kernel<<<dim3(4, 64), 256>>>(mask);
    out_proj_kernel<<<dim3(8, 32), 128, GEMM_SMEM>>>(bo);
    ln_kernel<<<B_*S_, 256>>>(query, ln_w, ln_b, out);
}

// round 16
// speedup vs baseline: 1.0513x; 1.0513x over previous
#include <cuda_runtime.h>
#include <cuda_fp16.h>
#include <math.h>
#include <stdint.h>

#define B_   4
#define S_   1024
#define D_   1024
#define H_   16
#define HD_  64
#define MTOT (B_*S_)

// ---- scratch (no cudaMalloc allowed) ----
__device__ __align__(16) __half g_Xh[3][MTOT*D_];   // q,k,v inputs in half
__device__ __align__(16) __half g_Wh[4][D_*D_];     // W in half, [k][n]
__device__ __align__(16) __half g_Qh[MTOT*D_];      // [B,H,S,HD]
__device__ __align__(16) __half g_Kh[MTOT*D_];
__device__ __align__(16) __half g_Vh[MTOT*D_];
__device__ __align__(16) __half g_attn_h[MTOT*D_];  // [B,S,D] half
__device__ __align__(16) float  g_proj[MTOT*D_];

__device__ __forceinline__ void mma_f16(float c[4], const uint32_t a[4],
                                        const uint32_t b[2]) {
    asm volatile(
        "mma.sync.aligned.m16n8k16.row.col.f32.f16.f16.f32 "
        "{%0,%1,%2,%3}, {%4,%5,%6,%7}, {%8,%9}, {%0,%1,%2,%3};"
        : "+f"(c[0]), "+f"(c[1]), "+f"(c[2]), "+f"(c[3])
        : "r"(a[0]), "r"(a[1]), "r"(a[2]), "r"(a[3]), "r"(b[0]), "r"(b[1]));
}

__device__ __forceinline__ void ldsm4(uint32_t r[4], const void* p) {
    uint32_t a = (uint32_t)__cvta_generic_to_shared(p);
    asm volatile("ldmatrix.sync.aligned.m8n8.x4.shared.b16 {%0,%1,%2,%3}, [%4];"
                 : "=r"(r[0]), "=r"(r[1]), "=r"(r[2]), "=r"(r[3]) : "r"(a));
}
__device__ __forceinline__ void ldsm4t(uint32_t r[4], const void* p) {
    uint32_t a = (uint32_t)__cvta_generic_to_shared(p);
    asm volatile("ldmatrix.sync.aligned.m8n8.x4.trans.shared.b16 {%0,%1,%2,%3}, [%4];"
                 : "=r"(r[0]), "=r"(r[1]), "=r"(r[2]), "=r"(r[3]) : "r"(a));
}
__device__ __forceinline__ uint32_t packh2(float x, float y) {
    __half2 h = __floats2half2_rn(x, y);
    return *(uint32_t*)&h;
}
__device__ __forceinline__ uint32_t hex2(uint32_t x) {
    uint32_t d;
    asm("ex2.approx.f16x2 %0, %1;" : "=r"(d) : "r"(x));
    return d;
}
__device__ __forceinline__ float fex2(float x) {
    float d;
    asm("ex2.approx.f32 %0, %1;" : "=f"(d) : "f"(x));
    return d;
}
__device__ __forceinline__ void cp16(void* smem, const void* gmem) {
    uint32_t s = (uint32_t)__cvta_generic_to_shared(smem);
    asm volatile("cp.async.cg.shared.global [%0], [%1], 16;\n" :: "r"(s), "l"(gmem));
}
__device__ __forceinline__ void cp_commit() {
    asm volatile("cp.async.commit_group;\n");
}
__device__ __forceinline__ void cp_wait1() {
    asm volatile("cp.async.wait_group 1;\n");
}

// ============================================================
// fused converters (both branches pure streaming converts)
// ============================================================
#define CONV_IN_BLKS (3 * (MTOT * D_ / 1024))
#define CONV_W_BLKS  (4 * (D_ * D_ / 1024))

__global__ __launch_bounds__(256) void conv_kernel(
    const float* __restrict__ q, const float* __restrict__ k,
    const float* __restrict__ v,
    const float* __restrict__ Wq, const float* __restrict__ Wk,
    const float* __restrict__ Wv, const float* __restrict__ Wo)
{
    const int blk = blockIdx.x;
    const float* src;
    __half* dst;
    int i;
    if (blk < CONV_IN_BLKS) {
        const int z  = blk / (MTOT * D_ / 1024);
        const int bx = blk % (MTOT * D_ / 1024);
        src = (z == 0) ? q : (z == 1) ? k : v;
        dst = g_Xh[z];
        i = (bx * 256 + threadIdx.x) * 4;
    } else {
        const int r  = blk - CONV_IN_BLKS;
        const int z  = r >> 10;
        const int bx = r & 1023;
        src = (z == 0) ? Wq : (z == 1) ? Wk : (z == 2) ? Wv : Wo;
        dst = g_Wh[z];
        i = (bx * 256 + threadIdx.x) * 4;
    }
    float4 f = *(const float4*)(src + i);
    *(__half2*)(dst + i)     = __floats2half2_rn(f.x, f.y);
    *(__half2*)(dst + i + 2) = __floats2half2_rn(f.z, f.w);
}

// ============================================================
// fp16 tensor-core GEMM: out = X[M,1024] @ W[1024,1024] + bias
// W stored [k][n]; B fragments via ldmatrix.trans (R14 config).
// BK=32, 2-stage static-smem cp.async double-buffer,
// 4 warps, warp tile 64x64.
// ============================================================
template <int MODE>
__device__ __forceinline__ void gemm_f16_body(
    const __half* __restrict__ X, const __half* __restrict__ Wn,
    const float* __restrict__ bias, void* outp)
{
    __shared__ __align__(16) __half As[2][128][40];   // [m][k]
    __shared__ __align__(16) __half Bs[2][32][136];   // [k][n]

    const int tid    = threadIdx.x;      // 0..127
    const int wid    = tid >> 5;         // 0..3
    const int lane   = tid & 31;
    const int warp_m = wid & 1;
    const int warp_n = wid >> 1;
    const int g      = lane >> 2;
    const int tg     = lane & 3;

    const int row0 = blockIdx.y * 128;
    const int col0 = blockIdx.x * 128;

    const int lrow = tid >> 1;           // 0..63
    const int loff = (tid & 1) * 16;

    const __half* Abase = X + (size_t)(row0 + lrow) * D_ + loff;

    auto load_stage = [&](int s, int k0) {
        #pragma unroll
        for (int p = 0; p < 2; p++) {
            const int r = p * 64;
            cp16(&As[s][lrow + r][loff],     Abase + (size_t)r * D_ + k0);
            cp16(&As[s][lrow + r][loff + 8], Abase + (size_t)r * D_ + k0 + 8);
        }
        #pragma unroll
        for (int qch = 0; qch < 4; qch++) {
            const int c  = qch * 128 + tid;
            const int br = c >> 4;            // 0..31 (k)
            const int bc = (c & 15) * 8;      // 0..120 (n)
            cp16(&Bs[s][br][bc], Wn + (size_t)(k0 + br) * D_ + col0 + bc);
        }
        cp_commit();
    };

    load_stage(0, 0);
    load_stage(1, 32);

    float acc[4][8][4];
    #pragma unroll
    for (int mt = 0; mt < 4; mt++)
        #pragma unroll
        for (int nt = 0; nt < 8; nt++)
            #pragma unroll
            for (int i = 0; i < 4; i++) acc[mt][nt][i] = 0.f;

    const int a_r = lane & 15;
    const int a_c = ((lane >> 4) & 1) * 8;
    const int t_r = ((lane >> 3) & 1) * 8 + (lane & 7);   // trans row (k)
    const int t_c = ((lane >> 4) & 1) * 8;                // trans col (n)

    const int NIT = D_ / 32;
    for (int it = 0; it < NIT; it++) {
        cp_wait1();
        __syncthreads();
        const int s = it & 1;

        #pragma unroll
        for (int ks = 0; ks < 2; ks++) {
            const int kb = ks * 16;
            uint32_t af[4][4];
            #pragma unroll
            for (int mt = 0; mt < 4; mt++)
                ldsm4(af[mt], &As[s][warp_m*64 + mt*16 + a_r][kb + a_c]);
            uint32_t bf[8][2];
            #pragma unroll
            for (int ntp = 0; ntp < 4; ntp++) {
                uint32_t t[4];
                ldsm4t(t, &Bs[s][kb + t_r][warp_n*64 + ntp*16 + t_c]);
                bf[2*ntp][0]   = t[0]; bf[2*ntp][1]   = t[1];
                bf[2*ntp+1][0] = t[2]; bf[2*ntp+1][1] = t[3];
            }
            #pragma unroll
            for (int mt = 0; mt < 4; mt++)
                #pragma unroll
                for (int nt = 0; nt < 8; nt++)
                    mma_f16(acc[mt][nt], af[mt], bf[nt]);
        }
        __syncthreads();
        const int knext = (it + 2 < NIT) ? (it + 2) * 32 : 0;
        load_stage(s, knext);
    }

    #pragma unroll
    for (int nt = 0; nt < 8; nt++) {
        const int c  = col0 + warp_n * 64 + nt * 8 + tg * 2;
        const float bx = bias[c];
        const float by = bias[c + 1];
        #pragma unroll
        for (int mt = 0; mt < 4; mt++) {
            const int r = row0 + warp_m * 64 + mt * 16 + g;
            if (MODE == 0) {
                __half* oh = (__half*)outp;
                __half2 v0 = __floats2half2_rn(acc[mt][nt][0] + bx, acc[mt][nt][1] + by);
                __half2 v1 = __floats2half2_rn(acc[mt][nt][2] + bx, acc[mt][nt][3] + by);
                const int h = c >> 6, d = c & 63;
                const int b0 = r >> 10,       s0 = r & (S_ - 1);
                const int b1 = (r + 8) >> 10, s1 = (r + 8) & (S_ - 1);
                *(__half2*)(&oh[(((size_t)(b0 * H_ + h)) * S_ + s0) * HD_ + d]) = v0;
                *(__half2*)(&oh[(((size_t)(b1 * H_ + h)) * S_ + s1) * HD_ + d]) = v1;
            } else {
                float* of = (float*)outp;
                float2 v0 = make_float2(acc[mt][nt][0] + bx, acc[mt][nt][1] + by);
                float2 v1 = make_float2(acc[mt][nt][2] + bx, acc[mt][nt][3] + by);
                *(float2*)(&of[(size_t)r * D_ + c])       = v0;
                *(float2*)(&of[(size_t)(r + 8) * D_ + c]) = v1;
            }
        }
    }
}

__global__ __launch_bounds__(128, 2) void qkv_proj_kernel(
    const float* __restrict__ bq, const float* __restrict__ bk,
    const float* __restrict__ bv)
{
    const int z = blockIdx.z;
    const float* bias = (z == 0) ? bq : (z == 1) ? bk : bv;
    __half* outp = (z == 0) ? g_Qh : (z == 1) ? g_Kh : g_Vh;
    gemm_f16_body<0>(g_Xh[z], g_Wh[z], bias, outp);
}

__global__ __launch_bounds__(128, 2) void out_proj_kernel(const float* __restrict__ bo)
{
    gemm_f16_body<1>(g_attn_h, g_Wh[3], bo, g_proj);
}

// ============================================================
// Flash attention (causal), fp16 TC, log2-domain softmax.
// Paired q-tiles (p, 7-p): every CTA = 18 KV-tile iterations.
// Mask row hoisted into smem ONCE per kernel (b-invariant).
// ============================================================
#define C_LOG2E 0.18033688011112042f   // 0.125 * log2(e)

__global__ __launch_bounds__(256, 2) void attn_kernel(const int* __restrict__ mask)
{
    __shared__ __align__(16) __half Ks[2][64][72];
    __shared__ __align__(16) __half Vs[2][64][72];
    __shared__ __align__(16) int    MskRow[S_];   // full mask row for batch b

    const int pr = blockIdx.x;        // 0..3
    const int bh = blockIdx.y;
    const int b  = bh >> 4;
    const int h  = bh & 15;

    const int tid  = threadIdx.x;
    const int wid  = tid >> 5;
    const int lane = tid & 31;
    const int g    = lane >> 2;
    const int tg   = lane & 3;
    const int m0   = wid * 16;

    const __half* __restrict__ Qg = g_Qh + (size_t)bh * S_ * HD_;
    const __half* __restrict__ Kg = g_Kh + (size_t)bh * S_ * HD_;
    const __half* __restrict__ Vg = g_Vh + (size_t)bh * S_ * HD_;

    // ---- hoist full mask row (1024 ints) once
    *(int4*)(&MskRow[tid * 4]) = *(const int4*)(mask + b * S_ + tid * 4);

    const int fr = tid >> 2;
    const int fc = (tid & 3) * 16;

    auto load_kv = [&](int j, int buf) {
        const __half* Krow = Kg + (size_t)(j*64 + fr) * HD_ + fc;
        const __half* Vrow = Vg + (size_t)(j*64 + fr) * HD_ + fc;
        cp16(&Ks[buf][fr][fc],     Krow);
        cp16(&Ks[buf][fr][fc + 8], Krow + 8);
        cp16(&Vs[buf][fr][fc],     Vrow);
        cp16(&Vs[buf][fr][fc + 8], Vrow + 8);
        cp_commit();
    };

    const int b_r = ((lane >> 4) & 1) * 8 + (lane & 7);
    const int b_c = ((lane >> 3) & 1) * 8;
    const int vrow_off = ((lane >> 3) & 1) * 8 + (lane & 7);
    const int vcol_off = ((lane >> 4) & 1) * 8;
    const uint32_t ONES_B[2] = {0x3C003C00u, 0x3C003C00u};

    #pragma unroll 1
    for (int half = 0; half < 2; half++) {
        const int qt   = (half == 0) ? (7 - pr) : pr;   // heavy first
        const int jmax = 2*qt + 1;

        load_kv(0, 0);
        load_kv(1, 1);

        const int qr0 = qt*128 + m0 + g;
        uint32_t qf[4][4];
        {
            const __half* q0 = Qg + (size_t)qr0 * HD_ + 2*tg;
            const __half* q1 = Qg + (size_t)(qr0 + 8) * HD_ + 2*tg;
            #pragma unroll
            for (int ks = 0; ks < 4; ks++) {
                qf[ks][0] = *(const uint32_t*)(q0 + ks*16);
                qf[ks][1] = *(const uint32_t*)(q1 + ks*16);
                qf[ks][2] = *(const uint32_t*)(q0 + ks*16 + 8);
                qf[ks][3] = *(const uint32_t*)(q1 + ks*16 + 8);
            }
        }

        float m_i[2] = {-1e30f, -1e30f};
        float lacc[4] = {0.f, 0.f, 0.f, 0.f};
        float o[8][4];
        #pragma unroll
        for (int dt = 0; dt < 8; dt++)
            #pragma unroll
            for (int i = 0; i < 4; i++) o[dt][i] = 0.f;

        for (int j = 0; j <= jmax; j++) {
            const int buf = j & 1;
            cp_wait1();
            __syncthreads();   // KV tile visible; also orders MskRow on iter 0

            // ---- S = Q K^T (16x64 per warp)
            float s[8][4];
            #pragma unroll
            for (int nt = 0; nt < 8; nt++)
                #pragma unroll
                for (int i = 0; i < 4; i++) s[nt][i] = 0.f;

            #pragma unroll
            for (int ks = 0; ks < 4; ks++) {
                const int kb = ks * 16;
                #pragma unroll
                for (int ntp = 0; ntp < 4; ntp++) {
                    uint32_t t[4];
                    ldsm4(t, &Ks[buf][ntp*16 + b_r][kb + b_c]);
                    uint32_t bfa[2] = {t[0], t[1]};
                    uint32_t bfb[2] = {t[2], t[3]};
                    mma_f16(s[2*ntp],     qf[ks], bfa);
                    mma_f16(s[2*ntp + 1], qf[ks], bfb);
                }
            }

            // ---- scale (log2 domain) + mask
            const bool diag = (j*64 + 63) > (qt*128 + m0);
            const int jbase = j * 64;
            #pragma unroll
            for (int nt = 0; nt < 8; nt++) {
                const int c0 = nt*8 + 2*tg;
                const float ma = (MskRow[jbase + c0]     == 0) ? -1e9f : 0.f;
                const float mb = (MskRow[jbase + c0 + 1] == 0) ? -1e9f : 0.f;
                s[nt][0] = s[nt][0] * C_LOG2E + ma;
                s[nt][1] = s[nt][1] * C_LOG2E + mb;
                s[nt][2] = s[nt][2] * C_LOG2E + ma;
                s[nt][3] = s[nt][3] * C_LOG2E + mb;
                if (diag) {
                    const int gc0 = jbase + c0;
                    if (gc0 > qr0)         s[nt][0] = -1e9f;
                    if (gc0 + 1 > qr0)     s[nt][1] = -1e9f;
                    if (gc0 > qr0 + 8)     s[nt][2] = -1e9f;
                    if (gc0 + 1 > qr0 + 8) s[nt][3] = -1e9f;
                }
            }

            // ---- online max (rows g, g+8)
            float rm0 = -1e30f, rm1 = -1e30f;
            #pragma unroll
            for (int nt = 0; nt < 8; nt++) {
                rm0 = fmaxf(rm0, fmaxf(s[nt][0], s[nt][1]));
                rm1 = fmaxf(rm1, fmaxf(s[nt][2], s[nt][3]));
            }
            rm0 = fmaxf(rm0, __shfl_xor_sync(0xffffffffu, rm0, 1));
            rm0 = fmaxf(rm0, __shfl_xor_sync(0xffffffffu, rm0, 2));
            rm1 = fmaxf(rm1, __shfl_xor_sync(0xffffffffu, rm1, 1));
            rm1 = fmaxf(rm1, __shfl_xor_sync(0xffffffffu, rm1, 2));

            const float mn0 = fmaxf(m_i[0], rm0);
            const float mn1 = fmaxf(m_i[1], rm1);
            const float corr0 = fex2(m_i[0] - mn0);
            const float corr1 = fex2(m_i[1] - mn1);
            m_i[0] = mn0; m_i[1] = mn1;

            // ---- P fragments via ex2.f16x2
            uint32_t af[4][4];
            #pragma unroll
            for (int ks = 0; ks < 4; ks++) {
                af[ks][0] = hex2(packh2(s[2*ks][0]     - mn0, s[2*ks][1]     - mn0));
                af[ks][1] = hex2(packh2(s[2*ks][2]     - mn1, s[2*ks][3]     - mn1));
                af[ks][2] = hex2(packh2(s[2*ks + 1][0] - mn0, s[2*ks + 1][1] - mn0));
                af[ks][3] = hex2(packh2(s[2*ks + 1][2] - mn1, s[2*ks + 1][3] - mn1));
            }

            // ---- rescale O and l by corr
            #pragma unroll
            for (int dt = 0; dt < 8; dt++) {
                o[dt][0] *= corr0; o[dt][1] *= corr0;
                o[dt][2] *= corr1; o[dt][3] *= corr1;
            }
            lacc[0] *= corr0; lacc[1] *= corr0;
            lacc[2] *= corr1; lacc[3] *= corr1;

            // ---- O += P @ V ; l += P @ ones
            #pragma unroll
            for (int ks = 0; ks < 4; ks++) {
                mma_f16(lacc, af[ks], ONES_B);
                #pragma unroll
                for (int dt2 = 0; dt2 < 4; dt2++) {
                    uint32_t t[4];
                    ldsm4t(t, &Vs[buf][ks*16 + vrow_off][dt2*16 + vcol_off]);
                    uint32_t bfa[2] = {t[0], t[1]};
                    uint32_t bfb[2] = {t[2], t[3]};
                    mma_f16(o[dt2*2],     af[ks], bfa);
                    mma_f16(o[dt2*2 + 1], af[ks], bfb);
                }
            }

            __syncthreads();
            const int jn = (j + 2 <= jmax) ? j + 2 : 0;
            load_kv(jn, buf);
        }

        const float inv0 = 1.f / lacc[0];
        const float inv1 = 1.f / lacc[2];
        #pragma unroll
        for (int dt = 0; dt < 8; dt++) {
            const int c = h*64 + dt*8 + 2*tg;
            *(__half2*)(&g_attn_h[((size_t)(b*S_ + qr0))*D_ + c]) =
                __floats2half2_rn(o[dt][0] * inv0, o[dt][1] * inv0);
            *(__half2*)(&g_attn_h[((size_t)(b*S_ + qr0 + 8))*D_ + c]) =
                __floats2half2_rn(o[dt][2] * inv1, o[dt][3] * inv1);
        }
    }
}

// ============================================================
// Residual add + LayerNorm, float4-vectorized, row in registers.
// ============================================================
__global__ __launch_bounds__(256) void ln_kernel(
    const float* __restrict__ query,
    const float* __restrict__ lw, const float* __restrict__ lb,
    float* __restrict__ out)
{
    __shared__ float red[8];
    const int r   = blockIdx.x;
    const int tid = threadIdx.x;
    const size_t base = (size_t)r * D_;

    float4 a = *(const float4*)(g_proj + base + tid * 4);
    float4 qv = *(const float4*)(query + base + tid * 4);
    float4 x;
    x.x = a.x + qv.x; x.y = a.y + qv.y;
    x.z = a.z + qv.z; x.w = a.w + qv.w;

    float s = x.x + x.y + x.z + x.w;
    #pragma unroll
    for (int off = 16; off >= 1; off >>= 1) s += __shfl_xor_sync(~0u, s, off);
    if ((tid & 31) == 0) red[tid >> 5] = s;
    __syncthreads();
    if (tid < 32) {
        float t = (tid < 8) ? red[tid] : 0.f;
        #pragma unroll
        for (int off = 4; off >= 1; off >>= 1) t += __shfl_xor_sync(~0u, t, off);
        if (tid == 0) red[0] = t;
    }
    __syncthreads();
    const float mean = red[0] * (1.f / (float)D_);
    __syncthreads();

    float4 d;
    d.x = x.x - mean; d.y = x.y - mean;
    d.z = x.z - mean; d.w = x.w - mean;
    float sv = d.x*d.x + d.y*d.y + d.z*d.z + d.w*d.w;
    #pragma unroll
    for (int off = 16; off >= 1; off >>= 1) sv += __shfl_xor_sync(~0u, sv, off);
    if ((tid & 31) == 0) red[tid >> 5] = sv;
    __syncthreads();
    if (tid < 32) {
        float t = (tid < 8) ? red[tid] : 0.f;
        #pragma unroll
        for (int off = 4; off >= 1; off >>= 1) t += __shfl_xor_sync(~0u, t, off);
        if (tid == 0) red[0] = t;
    }
    __syncthreads();
    const float var = red[0] * (1.f / (float)(D_ - 1));
    const float inv = 1.f / (sqrtf(var) + 1e-6f);

    float4 w = *(const float4*)(lw + tid * 4);
    float4 bb = *(const float4*)(lb + tid * 4);
    float4 o;
    o.x = w.x * d.x * inv + bb.x;
    o.y = w.y * d.y * inv + bb.y;
    o.z = w.z * d.z * inv + bb.z;
    o.w = w.w * d.w * inv + bb.w;
    *(float4*)(out + base + tid * 4) = o;
}

// ============================================================
extern "C" void kernel_launch(void* const* d_in, const int* in_sizes, int n_in,
                              void* d_out, int out_size)
{
    const float* query = (const float*)d_in[0];
    const float* key   = (const float*)d_in[1];
    const float* value = (const float*)d_in[2];
    const int*   mask  = (const int*)  d_in[3];
    const float* Wq    = (const float*)d_in[4];
    const float* bq    = (const float*)d_in[5];
    const float* Wk    = (const float*)d_in[6];
    const float* bk    = (const float*)d_in[7];
    const float* Wv    = (const float*)d_in[8];
    const float* bv    = (const float*)d_in[9];
    const float* Wo    = (const float*)d_in[10];
    const float* bo    = (const float*)d_in[11];
    const float* ln_w  = (const float*)d_in[12];
    const float* ln_b  = (const float*)d_in[13];
    float* out = (float*)d_out;

    conv_kernel<<<CONV_IN_BLKS + CONV_W_BLKS, 256>>>(query, key, value,
                                                     Wq, Wk, Wv, Wo);
    qkv_proj_kernel<<<dim3(8, 32, 3), 128>>>(bq, bk, bv);
    attn_kernel<<<dim3(4, 64), 256>>>(mask);
    out_proj_kernel<<<dim3(8, 32), 128>>>(bo);
    ln_kernel<<<B_*S_, 256>>>(query, ln_w, ln_b, out);
}